// round 2
// baseline (speedup 1.0000x reference)
#include <cuda_runtime.h>
#include <math.h>

// ---------------- problem constants ----------------
#define NB    64
#define NS    32
#define BS    2048            // NB*NS frames
#define D_MODEL 128
#define D_STATE 32
#define D_CONV  4
#define D_INNER 256
#define DT_RANK 8
#define CNN_OUT 3136
#define NA    18
#define INV255 (1.0f/255.0f)

// ---------------- scratch (static device globals; no allocation) ----------------
__device__ float g_act1[(size_t)BS*32*400];   // conv1 out: [img][32][20][20]
__device__ float g_act2[(size_t)BS*64*81];    // conv2 out: [img][64][9][9]
__device__ float g_act3[(size_t)BS*3136];     // conv3 out: [img][3136]
__device__ float g_feat[(size_t)BS*128];
__device__ float g_xz  [(size_t)BS*512];      // in_proj out (u_raw | z)
__device__ float g_u   [(size_t)BS*256];      // after causal conv1d + silu
__device__ float g_xdbl[(size_t)BS*72];       // x_proj out: [dt(8) | B(32) | C(32)]
__device__ float g_dt  [(size_t)BS*256];      // softplus(dt)
__device__ float g_yg  [NB*256];              // gated scan output at t=S-1
__device__ float g_w1t [256*32];              // conv1 weights [r][oc]
__device__ float g_w2t [512*64];              // conv2 weights [r][oc]
__device__ float g_w3t [576*64];              // conv3 weights [r][oc]

// ---------------- weight transpose (once per launch, coalesced consumers) ----------------
__global__ void prep_weights(const float* __restrict__ w1,
                             const float* __restrict__ w2,
                             const float* __restrict__ w3) {
    int idx = blockIdx.x * 256 + threadIdx.x;
    if (idx < 8192) {                 // conv1: 32 oc x 256 r
        int r = idx >> 5, oc = idx & 31;
        g_w1t[idx] = w1[oc * 256 + r];
    } else if (idx < 8192 + 32768) {  // conv2: 64 oc x 512 r
        int i = idx - 8192;
        int r = i >> 6, oc = i & 63;
        g_w2t[i] = w2[oc * 512 + r];
    } else if (idx < 8192 + 32768 + 36864) { // conv3: 64 oc x 576 r
        int i = idx - 40960;
        int r = i >> 6, oc = i & 63;
        g_w3t[i] = w3[oc * 576 + r];
    }
}

// ---------------- conv1: 4->32, 8x8, stride 4, 84x84 -> 20x20 ----------------
// one block per image; image (28224 f) + weights (8192 f) in SMEM
__global__ void __launch_bounds__(512) conv1_kernel(const float* __restrict__ x,
                                                    const float* __restrict__ bias) {
    extern __shared__ float sm[];
    float* in_s = sm;            // 28224 floats, rows of 84 are 16B-aligned (84%4==0)
    float* w_s  = sm + 28224;    // 8192 floats [r][oc]
    int img = blockIdx.x;
    const float4* xin4 = (const float4*)(x + (size_t)img * 28224);
    float4* in4 = (float4*)in_s;
    for (int i = threadIdx.x; i < 7056; i += 512) {
        float4 v = xin4[i];
        v.x *= INV255; v.y *= INV255; v.z *= INV255; v.w *= INV255;
        in4[i] = v;
    }
    for (int i = threadIdx.x; i < 8192; i += 512) w_s[i] = g_w1t[i];
    __syncthreads();

    if (threadIdx.x < 400) {
        int oy = threadIdx.x / 20, ox = threadIdx.x % 20;
        float acc[32];
#pragma unroll
        for (int j = 0; j < 32; j++) acc[j] = 0.f;
        const float4* w4 = (const float4*)w_s;
        for (int c = 0; c < 4; c++) {
#pragma unroll
            for (int ky = 0; ky < 8; ky++) {
                int iy = oy * 4 + ky;
                int b4 = c * 1764 + iy * 21 + ox;    // (c*84*84 + iy*84 + ox*4)/4
                float4 a = in4[b4], b = in4[b4 + 1];
                float in8[8] = {a.x,a.y,a.z,a.w,b.x,b.y,b.z,b.w};
#pragma unroll
                for (int kx = 0; kx < 8; kx++) {
                    float iv = in8[kx];
                    const float4* wp = w4 + (size_t)(c * 64 + ky * 8 + kx) * 8;
#pragma unroll
                    for (int j = 0; j < 8; j++) {
                        float4 wv = wp[j];
                        acc[4*j+0] += iv * wv.x;
                        acc[4*j+1] += iv * wv.y;
                        acc[4*j+2] += iv * wv.z;
                        acc[4*j+3] += iv * wv.w;
                    }
                }
            }
        }
        size_t base = (size_t)img * 12800 + threadIdx.x;
#pragma unroll
        for (int oc = 0; oc < 32; oc++) {
            float v = acc[oc] + bias[oc];
            g_act1[base + (size_t)oc * 400] = v > 0.f ? v : 0.f;
        }
    }
}

// ---------------- conv2: 32->64, 4x4, stride 2, 20x20 -> 9x9 ----------------
__global__ void __launch_bounds__(384) conv2_kernel(const float* __restrict__ bias) {
    extern __shared__ float sm[];
    float* in_s = sm;            // 12800
    float* w_s  = sm + 12800;    // 32768 [r][oc]
    int img = blockIdx.x;
    const float4* src4 = (const float4*)(g_act1 + (size_t)img * 12800);
    float4* in4 = (float4*)in_s;
    for (int i = threadIdx.x; i < 3200; i += 384) in4[i] = src4[i];
    const float4* wsrc4 = (const float4*)g_w2t;
    float4* w4s = (float4*)w_s;
    for (int i = threadIdx.x; i < 8192; i += 384) w4s[i] = wsrc4[i];
    __syncthreads();

    int g = threadIdx.x / 96;
    int p = threadIdx.x % 96;
    if (p < 81) {
        int oy = p / 9, ox = p % 9;
        int base = oy * 40 + ox * 2;     // oy*2*20 + ox*2
        float acc[16];
#pragma unroll
        for (int j = 0; j < 16; j++) acc[j] = 0.f;
        const float4* w4 = (const float4*)w_s;
        for (int c = 0; c < 32; c++) {
#pragma unroll
            for (int ky = 0; ky < 4; ky++) {
#pragma unroll
                for (int kx = 0; kx < 4; kx++) {
                    float iv = in_s[c * 400 + base + ky * 20 + kx];
                    const float4* wp = w4 + (size_t)(c * 16 + ky * 4 + kx) * 16 + g * 4;
#pragma unroll
                    for (int j = 0; j < 4; j++) {
                        float4 wv = wp[j];
                        acc[4*j+0] += iv * wv.x;
                        acc[4*j+1] += iv * wv.y;
                        acc[4*j+2] += iv * wv.z;
                        acc[4*j+3] += iv * wv.w;
                    }
                }
            }
        }
        size_t base_o = (size_t)img * 5184 + p;
#pragma unroll
        for (int j = 0; j < 16; j++) {
            int oc = g * 16 + j;
            float v = acc[j] + bias[oc];
            g_act2[base_o + (size_t)oc * 81] = v > 0.f ? v : 0.f;
        }
    }
}

// ---------------- conv3: 64->64, 3x3, stride 1, 9x9 -> 7x7 ----------------
__global__ void __launch_bounds__(256) conv3_kernel(const float* __restrict__ bias) {
    extern __shared__ float sm[];
    float* in_s = sm;           // 5184
    float* w_s  = sm + 5184;    // 36864 [r][oc]
    int img = blockIdx.x;
    const float4* src4 = (const float4*)(g_act2 + (size_t)img * 5184);
    float4* in4 = (float4*)in_s;
    for (int i = threadIdx.x; i < 1296; i += 256) in4[i] = src4[i];
    const float4* wsrc4 = (const float4*)g_w3t;
    float4* w4s = (float4*)w_s;
    for (int i = threadIdx.x; i < 9216; i += 256) w4s[i] = wsrc4[i];
    __syncthreads();

    int g = threadIdx.x / 64;
    int p = threadIdx.x % 64;
    if (p < 49) {
        int oy = p / 7, ox = p % 7;
        int base = oy * 9 + ox;
        float acc[16];
#pragma unroll
        for (int j = 0; j < 16; j++) acc[j] = 0.f;
        const float4* w4 = (const float4*)w_s;
        for (int c = 0; c < 64; c++) {
#pragma unroll
            for (int ky = 0; ky < 3; ky++) {
#pragma unroll
                for (int kx = 0; kx < 3; kx++) {
                    float iv = in_s[c * 81 + base + ky * 9 + kx];
                    const float4* wp = w4 + (size_t)(c * 9 + ky * 3 + kx) * 16 + g * 4;
#pragma unroll
                    for (int j = 0; j < 4; j++) {
                        float4 wv = wp[j];
                        acc[4*j+0] += iv * wv.x;
                        acc[4*j+1] += iv * wv.y;
                        acc[4*j+2] += iv * wv.z;
                        acc[4*j+3] += iv * wv.w;
                    }
                }
            }
        }
        size_t base_o = (size_t)img * 3136 + p;
#pragma unroll
        for (int j = 0; j < 16; j++) {
            int oc = g * 16 + j;
            float v = acc[j] + bias[oc];
            g_act3[base_o + (size_t)oc * 49] = v > 0.f ? v : 0.f;
        }
    }
}

// ---------------- generic GEMM: C[M,N] = A[M,K] @ W[N,K]^T (+bias)(+act) ----------------
template<int ACT>
__global__ void __launch_bounds__(256) gemm_tn(const float* __restrict__ A, int lda,
                                               const float* __restrict__ W, int ldw,
                                               const float* __restrict__ bias,
                                               float* __restrict__ C, int ldc,
                                               int M, int N, int K) {
    __shared__ float As[32][33];
    __shared__ float Ws[64][33];
    int row0 = blockIdx.x * 32, col0 = blockIdx.y * 64;
    int tx = threadIdx.x & 15;
    int ty = threadIdx.x >> 4;
    float acc[2][4] = {};
    for (int k0 = 0; k0 < K; k0 += 32) {
#pragma unroll
        for (int e = 0; e < 4; e++) {
            int idx = threadIdx.x + e * 256;
            int r = idx >> 5, cc = idx & 31;
            As[r][cc] = (row0 + r < M && k0 + cc < K) ? A[(size_t)(row0 + r) * lda + k0 + cc] : 0.f;
        }
#pragma unroll
        for (int e = 0; e < 8; e++) {
            int idx = threadIdx.x + e * 256;
            int r = idx >> 5, cc = idx & 31;
            Ws[r][cc] = (col0 + r < N && k0 + cc < K) ? W[(size_t)(col0 + r) * ldw + k0 + cc] : 0.f;
        }
        __syncthreads();
#pragma unroll
        for (int kk = 0; kk < 32; kk++) {
            float a0 = As[ty * 2 + 0][kk];
            float a1 = As[ty * 2 + 1][kk];
            float b0 = Ws[tx * 4 + 0][kk];
            float b1 = Ws[tx * 4 + 1][kk];
            float b2 = Ws[tx * 4 + 2][kk];
            float b3 = Ws[tx * 4 + 3][kk];
            acc[0][0] += a0 * b0; acc[0][1] += a0 * b1; acc[0][2] += a0 * b2; acc[0][3] += a0 * b3;
            acc[1][0] += a1 * b0; acc[1][1] += a1 * b1; acc[1][2] += a1 * b2; acc[1][3] += a1 * b3;
        }
        __syncthreads();
    }
#pragma unroll
    for (int i = 0; i < 2; i++) {
        int r = row0 + ty * 2 + i;
        if (r >= M) continue;
#pragma unroll
        for (int j = 0; j < 4; j++) {
            int cc = col0 + tx * 4 + j;
            if (cc >= N) continue;
            float v = acc[i][j];
            if (bias) v += bias[cc];
            if (ACT == 1) v = (v > 20.f) ? v : log1pf(__expf(v));  // softplus
            C[(size_t)r * ldc + cc] = v;
        }
    }
}

// ---------------- causal depthwise conv1d + silu ----------------
__global__ void conv1d_silu(const float* __restrict__ w, const float* __restrict__ b) {
    int idx = blockIdx.x * 256 + threadIdx.x;
    if (idx >= BS * 256) return;
    int bs = idx >> 8;        // frame
    int d  = idx & 255;
    int bb = bs >> 5, s = bs & 31;
    float acc = b[d];
#pragma unroll
    for (int k = 0; k < 4; k++) {
        int si = s - 3 + k;
        if (si >= 0) acc += g_xz[(size_t)(bb * 32 + si) * 512 + d] * w[d * 4 + k];
    }
    g_u[(size_t)bs * 256 + d] = acc / (1.f + __expf(-acc));
}

// ---------------- selective scan; contract with C only at t=S-1 ----------------
__global__ void scan_kernel(const float* __restrict__ A_log, const float* __restrict__ Dv) {
    int w = blockIdx.x * 8 + (threadIdx.x >> 5);
    int lane = threadIdx.x & 31;
    int bb = w >> 8, d = w & 255;
    float An = -__expf(A_log[d * 32 + lane]);
    float h = 0.f;
#pragma unroll 4
    for (int t = 0; t < 32; t++) {
        size_t bs = (size_t)(bb * 32 + t);
        float dtv = g_dt[bs * 256 + d];
        float uv  = g_u [bs * 256 + d];
        float Bv  = g_xdbl[bs * 72 + 8 + lane];
        h = __expf(dtv * An) * h + (dtv * uv) * Bv;
    }
    size_t bs_last = (size_t)(bb * 32 + 31);
    float Cv = g_xdbl[bs_last * 72 + 40 + lane];
    float y = h * Cv;
#pragma unroll
    for (int o = 16; o; o >>= 1) y += __shfl_xor_sync(0xffffffffu, y, o);
    if (lane == 0) {
        float ul = g_u[bs_last * 256 + d];
        y += Dv[d] * ul;
        float z = g_xz[bs_last * 512 + 256 + d];
        y *= z / (1.f + __expf(-z));
        g_yg[bb * 256 + d] = y;
    }
}

// ---------------- heads: out_proj (last step) + fc1 + fc2 + q ----------------
__global__ void __launch_bounds__(128) heads_kernel(
        const float* __restrict__ op_w,
        const float* __restrict__ fc1_w, const float* __restrict__ fc1_b,
        const float* __restrict__ fc2_w, const float* __restrict__ fc2_b,
        const float* __restrict__ q_w,  const float* __restrict__ q_b,
        float* __restrict__ out) {
    int b = blockIdx.x, tid = threadIdx.x;
    __shared__ float yg[256], lat[128], h1[128], h2[128];
    yg[tid]       = g_yg[b * 256 + tid];
    yg[tid + 128] = g_yg[b * 256 + tid + 128];
    __syncthreads();
    float acc = 0.f;
#pragma unroll 8
    for (int k = 0; k < 256; k++) acc += op_w[tid * 256 + k] * yg[k];
    lat[tid] = acc;
    out[NB * NA + b * 128 + tid] = acc;    // latent region after q region
    __syncthreads();
    acc = fc1_b[tid];
#pragma unroll 8
    for (int k = 0; k < 128; k++) acc += fc1_w[tid * 128 + k] * lat[k];
    h1[tid] = acc > 0.f ? acc : 0.f;
    __syncthreads();
    acc = fc2_b[tid];
#pragma unroll 8
    for (int k = 0; k < 128; k++) acc += fc2_w[tid * 128 + k] * h1[k];
    h2[tid] = acc > 0.f ? acc : 0.f;
    __syncthreads();
    if (tid < NA) {
        acc = q_b[tid];
#pragma unroll 8
        for (int k = 0; k < 128; k++) acc += q_w[tid * 128 + k] * h2[k];
        out[b * NA + tid] = acc;
    }
}

// ---------------- host launcher ----------------
extern "C" void kernel_launch(void* const* d_in, const int* in_sizes, int n_in,
                              void* d_out, int out_size) {
    const float* x         = (const float*)d_in[0];
    const float* conv1_w   = (const float*)d_in[1];
    const float* conv1_b   = (const float*)d_in[2];
    const float* conv2_w   = (const float*)d_in[3];
    const float* conv2_b   = (const float*)d_in[4];
    const float* conv3_w   = (const float*)d_in[5];
    const float* conv3_b   = (const float*)d_in[6];
    const float* feat_w    = (const float*)d_in[7];
    const float* feat_b    = (const float*)d_in[8];
    const float* in_proj_w = (const float*)d_in[9];
    const float* conv1d_w  = (const float*)d_in[10];
    const float* conv1d_b  = (const float*)d_in[11];
    const float* x_proj_w  = (const float*)d_in[12];
    const float* dt_proj_w = (const float*)d_in[13];
    const float* dt_proj_b = (const float*)d_in[14];
    const float* A_log     = (const float*)d_in[15];
    const float* Dvec      = (const float*)d_in[16];
    const float* out_proj_w= (const float*)d_in[17];
    const float* fc1_w     = (const float*)d_in[18];
    const float* fc1_b     = (const float*)d_in[19];
    const float* fc2_w     = (const float*)d_in[20];
    const float* fc2_b     = (const float*)d_in[21];
    const float* q_w       = (const float*)d_in[22];
    const float* q_b       = (const float*)d_in[23];
    float* out = (float*)d_out;

    // CRITICAL: resolve real device addresses of __device__ globals.
    // Passing the symbol name from host code passes the host shadow address
    // (which GB300's ATS happily dereferences into host memory — silent wrong answers).
    float *p_act3, *p_feat, *p_xz, *p_u, *p_xdbl, *p_dt;
    cudaGetSymbolAddress((void**)&p_act3, g_act3);
    cudaGetSymbolAddress((void**)&p_feat, g_feat);
    cudaGetSymbolAddress((void**)&p_xz,   g_xz);
    cudaGetSymbolAddress((void**)&p_u,    g_u);
    cudaGetSymbolAddress((void**)&p_xdbl, g_xdbl);
    cudaGetSymbolAddress((void**)&p_dt,   g_dt);

    cudaFuncSetAttribute(conv1_kernel, cudaFuncAttributeMaxDynamicSharedMemorySize, 145664);
    cudaFuncSetAttribute(conv2_kernel, cudaFuncAttributeMaxDynamicSharedMemorySize, 182272);
    cudaFuncSetAttribute(conv3_kernel, cudaFuncAttributeMaxDynamicSharedMemorySize, 168192);

    prep_weights<<<304, 256>>>(conv1_w, conv2_w, conv3_w);
    conv1_kernel<<<BS, 512, 145664>>>(x, conv1_b);
    conv2_kernel<<<BS, 384, 182272>>>(conv2_b);
    conv3_kernel<<<BS, 256, 168192>>>(conv3_b);

    // feat: (2048 x 3136) @ (128 x 3136)^T + bias
    gemm_tn<0><<<dim3(64, 2), 256>>>(p_act3, 3136, feat_w, 3136, feat_b, p_feat, 128,
                                     BS, 128, 3136);
    // in_proj: (2048 x 128) @ (512 x 128)^T
    gemm_tn<0><<<dim3(64, 8), 256>>>(p_feat, 128, in_proj_w, 128, (const float*)nullptr,
                                     p_xz, 512, BS, 512, 128);
    conv1d_silu<<<(BS * 256 + 255) / 256, 256>>>(conv1d_w, conv1d_b);
    // x_proj: (2048 x 256) @ (72 x 256)^T
    gemm_tn<0><<<dim3(64, 2), 256>>>(p_u, 256, x_proj_w, 256, (const float*)nullptr,
                                     p_xdbl, 72, BS, 72, 256);
    // dt: (2048 x 8) @ (256 x 8)^T + bias, softplus
    gemm_tn<1><<<dim3(64, 4), 256>>>(p_xdbl, 72, dt_proj_w, 8, dt_proj_b,
                                     p_dt, 256, BS, 256, 8);
    scan_kernel<<<BS, 256>>>(A_log, Dvec);
    heads_kernel<<<NB, 128>>>(out_proj_w, fc1_w, fc1_b, fc2_w, fc2_b, q_w, q_b, out);
}

// round 3
// speedup vs baseline: 1.0023x; 1.0023x over previous
#include <cuda_runtime.h>
#include <math.h>

// ---------------- problem constants ----------------
#define NB    64
#define NS    32
#define BS    2048            // NB*NS frames
#define D_MODEL 128
#define D_STATE 32
#define D_CONV  4
#define D_INNER 256
#define DT_RANK 8
#define CNN_OUT 3136
#define NA    18
#define INV255 (1.0f/255.0f)

// ---------------- scratch (static device globals; no allocation) ----------------
__device__ float g_act1[(size_t)BS*32*400];   // conv1 out: [img][32][20][20]
__device__ float g_act2[(size_t)BS*64*81];    // conv2 out: [img][64][9][9]
__device__ float g_act3[(size_t)BS*3136];     // conv3 out: [img][3136]
__device__ float g_feat[(size_t)BS*128];
__device__ float g_xz  [(size_t)BS*512];      // in_proj out (u_raw | z)
__device__ float g_u   [(size_t)BS*256];      // after causal conv1d + silu
__device__ float g_xdbl[(size_t)BS*72];       // x_proj out: [dt(8) | B(32) | C(32)]
__device__ float g_dt  [(size_t)BS*256];      // softplus(dt)
__device__ float g_yg  [NB*256];              // gated scan output at t=S-1
__device__ float g_w1t [256*32];              // conv1 weights [r][oc]
__device__ float g_w2t [512*64];              // conv2 weights [r][oc]
__device__ float g_w3t [576*64];              // conv3 weights [r][oc]

// ---------------- weight transpose (once per launch, coalesced consumers) ----------------
__global__ void prep_weights(const float* __restrict__ w1,
                             const float* __restrict__ w2,
                             const float* __restrict__ w3) {
    int idx = blockIdx.x * 256 + threadIdx.x;
    if (idx < 8192) {                 // conv1: 32 oc x 256 r
        int r = idx >> 5, oc = idx & 31;
        g_w1t[idx] = w1[oc * 256 + r];
    } else if (idx < 8192 + 32768) {  // conv2: 64 oc x 512 r
        int i = idx - 8192;
        int r = i >> 6, oc = i & 63;
        g_w2t[i] = w2[oc * 512 + r];
    } else if (idx < 8192 + 32768 + 36864) { // conv3: 64 oc x 576 r
        int i = idx - 40960;
        int r = i >> 6, oc = i & 63;
        g_w3t[i] = w3[oc * 576 + r];
    }
}

// ---------------- conv1: 4->32, 8x8, stride 4, 84x84 -> 20x20 ----------------
// one block per image; 800 threads = 2 oc-groups x 400 pixels (100% active)
__global__ void __launch_bounds__(800) conv1_kernel(const float* __restrict__ x,
                                                    const float* __restrict__ bias) {
    extern __shared__ float sm[];
    float* in_s = sm;            // 28224 floats
    float* w_s  = sm + 28224;    // 8192 floats [r][oc]
    int img = blockIdx.x;
    const float4* xin4 = (const float4*)(x + (size_t)img * 28224);
    float4* in4 = (float4*)in_s;
    for (int i = threadIdx.x; i < 7056; i += 800) {
        float4 v = xin4[i];
        v.x *= INV255; v.y *= INV255; v.z *= INV255; v.w *= INV255;
        in4[i] = v;
    }
    for (int i = threadIdx.x; i < 8192; i += 800) w_s[i] = g_w1t[i];
    __syncthreads();

    int g = threadIdx.x / 400;     // 0..1 -> 16 oc each
    int p = threadIdx.x % 400;
    int oy = p / 20, ox = p % 20;
    float acc[16];
#pragma unroll
    for (int j = 0; j < 16; j++) acc[j] = 0.f;
    const float4* w4 = (const float4*)w_s;
    for (int c = 0; c < 4; c++) {
#pragma unroll
        for (int ky = 0; ky < 8; ky++) {
            int iy = oy * 4 + ky;
            int b4 = c * 1764 + iy * 21 + ox;
            float4 a = in4[b4], b = in4[b4 + 1];
            float in8[8] = {a.x,a.y,a.z,a.w,b.x,b.y,b.z,b.w};
#pragma unroll
            for (int kx = 0; kx < 8; kx++) {
                float iv = in8[kx];
                const float4* wp = w4 + (size_t)(c * 64 + ky * 8 + kx) * 8 + g * 4;
#pragma unroll
                for (int j = 0; j < 4; j++) {
                    float4 wv = wp[j];
                    acc[4*j+0] += iv * wv.x;
                    acc[4*j+1] += iv * wv.y;
                    acc[4*j+2] += iv * wv.z;
                    acc[4*j+3] += iv * wv.w;
                }
            }
        }
    }
    size_t base = (size_t)img * 12800 + p;
#pragma unroll
    for (int j = 0; j < 16; j++) {
        int oc = g * 16 + j;
        float v = acc[j] + bias[oc];
        g_act1[base + (size_t)oc * 400] = v > 0.f ? v : 0.f;
    }
}

// ---------------- conv2: 32->64, 4x4, stride 2, 20x20 -> 9x9 ----------------
// 768 threads = 8 groups x 8 oc x 96 pixel-slots (81 active)
__global__ void __launch_bounds__(768) conv2_kernel(const float* __restrict__ bias) {
    extern __shared__ float sm[];
    float* in_s = sm;            // 12800
    float* w_s  = sm + 12800;    // 32768 [r][oc]
    int img = blockIdx.x;
    const float4* src4 = (const float4*)(g_act1 + (size_t)img * 12800);
    float4* in4 = (float4*)in_s;
    for (int i = threadIdx.x; i < 3200; i += 768) in4[i] = src4[i];
    const float4* wsrc4 = (const float4*)g_w2t;
    float4* w4s = (float4*)w_s;
    for (int i = threadIdx.x; i < 8192; i += 768) w4s[i] = wsrc4[i];
    __syncthreads();

    int g = threadIdx.x / 96;     // 0..7 -> 8 oc each (warp-uniform: 96 = 3 warps)
    int p = threadIdx.x % 96;
    if (p < 81) {
        int oy = p / 9, ox = p % 9;
        int base = oy * 40 + ox * 2;
        float acc[8];
#pragma unroll
        for (int j = 0; j < 8; j++) acc[j] = 0.f;
        const float4* w4 = (const float4*)w_s;
        for (int c = 0; c < 32; c++) {
#pragma unroll
            for (int ky = 0; ky < 4; ky++) {
#pragma unroll
                for (int kx = 0; kx < 4; kx++) {
                    float iv = in_s[c * 400 + base + ky * 20 + kx];
                    const float4* wp = w4 + (size_t)(c * 16 + ky * 4 + kx) * 16 + g * 2;
                    float4 w0 = wp[0], w1 = wp[1];
                    acc[0] += iv * w0.x; acc[1] += iv * w0.y;
                    acc[2] += iv * w0.z; acc[3] += iv * w0.w;
                    acc[4] += iv * w1.x; acc[5] += iv * w1.y;
                    acc[6] += iv * w1.z; acc[7] += iv * w1.w;
                }
            }
        }
        size_t base_o = (size_t)img * 5184 + p;
#pragma unroll
        for (int j = 0; j < 8; j++) {
            int oc = g * 8 + j;
            float v = acc[j] + bias[oc];
            g_act2[base_o + (size_t)oc * 81] = v > 0.f ? v : 0.f;
        }
    }
}

// ---------------- conv3: 64->64, 3x3, stride 1, 9x9 -> 7x7 ----------------
// 3 images per block, 768 threads; weights staged once, shared across images
__global__ void __launch_bounds__(768) conv3_kernel(const float* __restrict__ bias) {
    extern __shared__ float sm[];
    float* w_s  = sm;            // 36864 [r][oc]
    float* in_s = sm + 36864;    // 3*5184
    int img0 = blockIdx.x * 3;
    const float4* wsrc4 = (const float4*)g_w3t;
    float4* w4s = (float4*)w_s;
    for (int i = threadIdx.x; i < 9216; i += 768) w4s[i] = wsrc4[i];
    float4* in4 = (float4*)in_s;
    for (int i = threadIdx.x; i < 3888; i += 768) {
        int il = i / 1296;       // which image slot
        if (img0 + il < BS) {
            const float4* src4 = (const float4*)(g_act2 + (size_t)(img0 + il) * 5184);
            in4[i] = src4[i - il * 1296];
        }
    }
    __syncthreads();

    int il  = threadIdx.x / 256;     // image slot 0..2
    int sub = threadIdx.x % 256;
    int g = sub / 64;                // 0..3 -> 16 oc each (warp-uniform: 64 = 2 warps)
    int p = sub % 64;
    int img = img0 + il;
    if (p < 49 && img < BS) {
        int oy = p / 7, ox = p % 7;
        int base = il * 5184 + oy * 9 + ox;
        float acc[16];
#pragma unroll
        for (int j = 0; j < 16; j++) acc[j] = 0.f;
        const float4* w4 = (const float4*)w_s;
        for (int c = 0; c < 64; c++) {
#pragma unroll
            for (int ky = 0; ky < 3; ky++) {
#pragma unroll
                for (int kx = 0; kx < 3; kx++) {
                    float iv = in_s[c * 81 + base + ky * 9 + kx];
                    const float4* wp = w4 + (size_t)(c * 9 + ky * 3 + kx) * 16 + g * 4;
#pragma unroll
                    for (int j = 0; j < 4; j++) {
                        float4 wv = wp[j];
                        acc[4*j+0] += iv * wv.x;
                        acc[4*j+1] += iv * wv.y;
                        acc[4*j+2] += iv * wv.z;
                        acc[4*j+3] += iv * wv.w;
                    }
                }
            }
        }
        size_t base_o = (size_t)img * 3136 + p;
#pragma unroll
        for (int j = 0; j < 16; j++) {
            int oc = g * 16 + j;
            float v = acc[j] + bias[oc];
            g_act3[base_o + (size_t)oc * 49] = v > 0.f ? v : 0.f;
        }
    }
}

// ---------------- generic GEMM: C[M,N] = A[M,K] @ W[N,K]^T (+bias)(+act) ----------------
template<int ACT>
__global__ void __launch_bounds__(256) gemm_tn(const float* __restrict__ A, int lda,
                                               const float* __restrict__ W, int ldw,
                                               const float* __restrict__ bias,
                                               float* __restrict__ C, int ldc,
                                               int M, int N, int K) {
    __shared__ float As[32][33];
    __shared__ float Ws[64][33];
    int row0 = blockIdx.x * 32, col0 = blockIdx.y * 64;
    int tx = threadIdx.x & 15;
    int ty = threadIdx.x >> 4;
    float acc[2][4] = {};
    for (int k0 = 0; k0 < K; k0 += 32) {
#pragma unroll
        for (int e = 0; e < 4; e++) {
            int idx = threadIdx.x + e * 256;
            int r = idx >> 5, cc = idx & 31;
            As[r][cc] = (row0 + r < M && k0 + cc < K) ? A[(size_t)(row0 + r) * lda + k0 + cc] : 0.f;
        }
#pragma unroll
        for (int e = 0; e < 8; e++) {
            int idx = threadIdx.x + e * 256;
            int r = idx >> 5, cc = idx & 31;
            Ws[r][cc] = (col0 + r < N && k0 + cc < K) ? W[(size_t)(col0 + r) * ldw + k0 + cc] : 0.f;
        }
        __syncthreads();
#pragma unroll
        for (int kk = 0; kk < 32; kk++) {
            float a0 = As[ty * 2 + 0][kk];
            float a1 = As[ty * 2 + 1][kk];
            float b0 = Ws[tx * 4 + 0][kk];
            float b1 = Ws[tx * 4 + 1][kk];
            float b2 = Ws[tx * 4 + 2][kk];
            float b3 = Ws[tx * 4 + 3][kk];
            acc[0][0] += a0 * b0; acc[0][1] += a0 * b1; acc[0][2] += a0 * b2; acc[0][3] += a0 * b3;
            acc[1][0] += a1 * b0; acc[1][1] += a1 * b1; acc[1][2] += a1 * b2; acc[1][3] += a1 * b3;
        }
        __syncthreads();
    }
#pragma unroll
    for (int i = 0; i < 2; i++) {
        int r = row0 + ty * 2 + i;
        if (r >= M) continue;
#pragma unroll
        for (int j = 0; j < 4; j++) {
            int cc = col0 + tx * 4 + j;
            if (cc >= N) continue;
            float v = acc[i][j];
            if (bias) v += bias[cc];
            if (ACT == 1) v = (v > 20.f) ? v : log1pf(__expf(v));  // softplus
            C[(size_t)r * ldc + cc] = v;
        }
    }
}

// ---------------- causal depthwise conv1d + silu ----------------
__global__ void conv1d_silu(const float* __restrict__ w, const float* __restrict__ b) {
    int idx = blockIdx.x * 256 + threadIdx.x;
    if (idx >= BS * 256) return;
    int bs = idx >> 8;        // frame
    int d  = idx & 255;
    int bb = bs >> 5, s = bs & 31;
    float acc = b[d];
#pragma unroll
    for (int k = 0; k < 4; k++) {
        int si = s - 3 + k;
        if (si >= 0) acc += g_xz[(size_t)(bb * 32 + si) * 512 + d] * w[d * 4 + k];
    }
    g_u[(size_t)bs * 256 + d] = acc / (1.f + __expf(-acc));
}

// ---------------- selective scan; contract with C only at t=S-1 ----------------
__global__ void scan_kernel(const float* __restrict__ A_log, const float* __restrict__ Dv) {
    int w = blockIdx.x * 8 + (threadIdx.x >> 5);
    int lane = threadIdx.x & 31;
    int bb = w >> 8, d = w & 255;
    float An = -__expf(A_log[d * 32 + lane]);
    float h = 0.f;
#pragma unroll 4
    for (int t = 0; t < 32; t++) {
        size_t bs = (size_t)(bb * 32 + t);
        float dtv = g_dt[bs * 256 + d];
        float uv  = g_u [bs * 256 + d];
        float Bv  = g_xdbl[bs * 72 + 8 + lane];
        h = __expf(dtv * An) * h + (dtv * uv) * Bv;
    }
    size_t bs_last = (size_t)(bb * 32 + 31);
    float Cv = g_xdbl[bs_last * 72 + 40 + lane];
    float y = h * Cv;
#pragma unroll
    for (int o = 16; o; o >>= 1) y += __shfl_xor_sync(0xffffffffu, y, o);
    if (lane == 0) {
        float ul = g_u[bs_last * 256 + d];
        y += Dv[d] * ul;
        float z = g_xz[bs_last * 512 + 256 + d];
        y *= z / (1.f + __expf(-z));
        g_yg[bb * 256 + d] = y;
    }
}

// ---------------- heads: out_proj (last step) + fc1 + fc2 + q ----------------
__global__ void __launch_bounds__(128) heads_kernel(
        const float* __restrict__ op_w,
        const float* __restrict__ fc1_w, const float* __restrict__ fc1_b,
        const float* __restrict__ fc2_w, const float* __restrict__ fc2_b,
        const float* __restrict__ q_w,  const float* __restrict__ q_b,
        float* __restrict__ out) {
    int b = blockIdx.x, tid = threadIdx.x;
    __shared__ float yg[256], lat[128], h1[128], h2[128];
    yg[tid]       = g_yg[b * 256 + tid];
    yg[tid + 128] = g_yg[b * 256 + tid + 128];
    __syncthreads();
    float acc = 0.f;
#pragma unroll 8
    for (int k = 0; k < 256; k++) acc += op_w[tid * 256 + k] * yg[k];
    lat[tid] = acc;
    out[NB * NA + b * 128 + tid] = acc;    // latent region after q region
    __syncthreads();
    acc = fc1_b[tid];
#pragma unroll 8
    for (int k = 0; k < 128; k++) acc += fc1_w[tid * 128 + k] * lat[k];
    h1[tid] = acc > 0.f ? acc : 0.f;
    __syncthreads();
    acc = fc2_b[tid];
#pragma unroll 8
    for (int k = 0; k < 128; k++) acc += fc2_w[tid * 128 + k] * h1[k];
    h2[tid] = acc > 0.f ? acc : 0.f;
    __syncthreads();
    if (tid < NA) {
        acc = q_b[tid];
#pragma unroll 8
        for (int k = 0; k < 128; k++) acc += q_w[tid * 128 + k] * h2[k];
        out[b * NA + tid] = acc;
    }
}

// ---------------- host launcher ----------------
extern "C" void kernel_launch(void* const* d_in, const int* in_sizes, int n_in,
                              void* d_out, int out_size) {
    const float* x         = (const float*)d_in[0];
    const float* conv1_w   = (const float*)d_in[1];
    const float* conv1_b   = (const float*)d_in[2];
    const float* conv2_w   = (const float*)d_in[3];
    const float* conv2_b   = (const float*)d_in[4];
    const float* conv3_w   = (const float*)d_in[5];
    const float* conv3_b   = (const float*)d_in[6];
    const float* feat_w    = (const float*)d_in[7];
    const float* feat_b    = (const float*)d_in[8];
    const float* in_proj_w = (const float*)d_in[9];
    const float* conv1d_w  = (const float*)d_in[10];
    const float* conv1d_b  = (const float*)d_in[11];
    const float* x_proj_w  = (const float*)d_in[12];
    const float* dt_proj_w = (const float*)d_in[13];
    const float* dt_proj_b = (const float*)d_in[14];
    const float* A_log     = (const float*)d_in[15];
    const float* Dvec      = (const float*)d_in[16];
    const float* out_proj_w= (const float*)d_in[17];
    const float* fc1_w     = (const float*)d_in[18];
    const float* fc1_b     = (const float*)d_in[19];
    const float* fc2_w     = (const float*)d_in[20];
    const float* fc2_b     = (const float*)d_in[21];
    const float* q_w       = (const float*)d_in[22];
    const float* q_b       = (const float*)d_in[23];
    float* out = (float*)d_out;

    // Resolve real device addresses of __device__ globals (host shadow trap on GB300/ATS).
    float *p_act3, *p_feat, *p_xz, *p_u, *p_xdbl, *p_dt;
    cudaGetSymbolAddress((void**)&p_act3, g_act3);
    cudaGetSymbolAddress((void**)&p_feat, g_feat);
    cudaGetSymbolAddress((void**)&p_xz,   g_xz);
    cudaGetSymbolAddress((void**)&p_u,    g_u);
    cudaGetSymbolAddress((void**)&p_xdbl, g_xdbl);
    cudaGetSymbolAddress((void**)&p_dt,   g_dt);

    cudaFuncSetAttribute(conv1_kernel, cudaFuncAttributeMaxDynamicSharedMemorySize, 145664);
    cudaFuncSetAttribute(conv2_kernel, cudaFuncAttributeMaxDynamicSharedMemorySize, 182272);
    cudaFuncSetAttribute(conv3_kernel, cudaFuncAttributeMaxDynamicSharedMemorySize, 209664);

    prep_weights<<<304, 256>>>(conv1_w, conv2_w, conv3_w);
    conv1_kernel<<<BS, 800, 145664>>>(x, conv1_b);
    conv2_kernel<<<BS, 768, 182272>>>(conv2_b);
    conv3_kernel<<<(BS + 2) / 3, 768, 209664>>>(conv3_b);

    // feat: (2048 x 3136) @ (128 x 3136)^T + bias
    gemm_tn<0><<<dim3(64, 2), 256>>>(p_act3, 3136, feat_w, 3136, feat_b, p_feat, 128,
                                     BS, 128, 3136);
    // in_proj: (2048 x 128) @ (512 x 128)^T
    gemm_tn<0><<<dim3(64, 8), 256>>>(p_feat, 128, in_proj_w, 128, (const float*)nullptr,
                                     p_xz, 512, BS, 512, 128);
    conv1d_silu<<<(BS * 256 + 255) / 256, 256>>>(conv1d_w, conv1d_b);
    // x_proj: (2048 x 256) @ (72 x 256)^T
    gemm_tn<0><<<dim3(64, 2), 256>>>(p_u, 256, x_proj_w, 256, (const float*)nullptr,
                                     p_xdbl, 72, BS, 72, 256);
    // dt: (2048 x 8) @ (256 x 8)^T + bias, softplus
    gemm_tn<1><<<dim3(64, 4), 256>>>(p_xdbl, 72, dt_proj_w, 8, dt_proj_b,
                                     p_dt, 256, BS, 256, 8);
    scan_kernel<<<BS, 256>>>(A_log, Dvec);
    heads_kernel<<<NB, 128>>>(out_proj_w, fc1_w, fc1_b, fc2_w, fc2_b, q_w, q_b, out);
}

// round 4
// speedup vs baseline: 1.5822x; 1.5786x over previous
#include <cuda_runtime.h>
#include <math.h>

// ---------------- problem constants ----------------
#define NB    64
#define NS    32
#define BS    2048            // NB*NS frames
#define D_MODEL 128
#define D_STATE 32
#define D_CONV  4
#define D_INNER 256
#define DT_RANK 8
#define CNN_OUT 3136
#define NA    18
#define INV255 (1.0f/255.0f)

typedef unsigned long long ull;

// ---------------- scratch (static device globals; no allocation) ----------------
__device__ float g_act1[(size_t)BS*32*400];   // conv1 out: [img][32][20][20]
__device__ float g_act2[(size_t)BS*64*81];    // conv2 out: [img][64][9][9]
__device__ float g_act3[(size_t)BS*3136];     // conv3 out: [img][3136]
__device__ float g_feat[(size_t)BS*128];
__device__ float g_xz  [(size_t)BS*512];      // in_proj out (u_raw | z)
__device__ float g_u   [(size_t)BS*256];      // after causal conv1d + silu
__device__ float g_xdbl[(size_t)BS*72];       // x_proj out: [dt(8) | B(32) | C(32)]
__device__ float g_dt  [(size_t)BS*256];      // softplus(dt)
__device__ float g_yg  [NB*256];              // gated scan output at t=S-1
__device__ float g_w1t [256*32];              // conv1 weights [r][oc]
__device__ float g_w2t [512*64];              // conv2 weights [r][oc]
__device__ float g_w3t [576*64];              // conv3 weights [r][oc]

// ---------------- f32x2 helpers (sm_103a packed fp32 FMA) ----------------
__device__ __forceinline__ void ffma2(ull& d, ull a, ull b) {
    asm("fma.rn.f32x2 %0, %1, %2, %0;" : "+l"(d) : "l"(a), "l"(b));
}
__device__ __forceinline__ ull pack2(float v) {
    ull r;
    asm("mov.b64 %0, {%1, %1};" : "=l"(r) : "f"(v));
    return r;
}
__device__ __forceinline__ float2 unpack2(ull d) {
    float2 f;
    asm("mov.b64 {%0, %1}, %2;" : "=f"(f.x), "=f"(f.y) : "l"(d));
    return f;
}

// ---------------- weight transpose (once per launch) ----------------
__global__ void prep_weights(const float* __restrict__ w1,
                             const float* __restrict__ w2,
                             const float* __restrict__ w3) {
    int idx = blockIdx.x * 256 + threadIdx.x;
    if (idx < 8192) {                 // conv1: 32 oc x 256 r
        int r = idx >> 5, oc = idx & 31;
        g_w1t[idx] = w1[oc * 256 + r];
    } else if (idx < 8192 + 32768) {  // conv2: 64 oc x 512 r
        int i = idx - 8192;
        int r = i >> 6, oc = i & 63;
        g_w2t[i] = w2[oc * 512 + r];
    } else if (idx < 8192 + 32768 + 36864) { // conv3: 64 oc x 576 r
        int i = idx - 40960;
        int r = i >> 6, oc = i & 63;
        g_w3t[i] = w3[oc * 576 + r];
    }
}

// ---------------- conv1: 4->32, 8x8, stride 4, 84x84 -> 20x20 ----------------
// 1 image/block, 320 threads = (oy 0..19) x (ocg 0..3 of 8 oc) x (cc 0..3 of 5 px)
// input in smem (rows of 84f = 16B-aligned); weights via LDG (L2, 1 line/tap)
__global__ void __launch_bounds__(320, 2) conv1_kernel(const float* __restrict__ x,
                                                       const float* __restrict__ bias) {
    extern __shared__ float sm[];            // 28224 floats
    int img = blockIdx.x;
    const float4* xin4 = (const float4*)(x + (size_t)img * 28224);
    float4* in4 = (float4*)sm;
    for (int i = threadIdx.x; i < 7056; i += 320) {
        float4 v = xin4[i];
        v.x *= INV255; v.y *= INV255; v.z *= INV255; v.w *= INV255;
        in4[i] = v;
    }
    __syncthreads();

    int cc  = threadIdx.x & 3;       // 5-px column chunk
    int ocg = (threadIdx.x >> 2) & 3;
    int oy  = threadIdx.x >> 4;

    ull acc[5][4];
#pragma unroll
    for (int p = 0; p < 5; p++)
#pragma unroll
        for (int j = 0; j < 4; j++) acc[p][j] = 0ull;

#pragma unroll 1
    for (int c = 0; c < 4; c++) {
#pragma unroll 1
        for (int ky = 0; ky < 8; ky++) {
            int iy = oy * 4 + ky;
            const float4* rp = in4 + c * 1764 + iy * 21 + cc * 5;
            float4 q0 = rp[0], q1 = rp[1], q2 = rp[2], q3 = rp[3], q4 = rp[4], q5 = rp[5];
            float row[24] = {q0.x,q0.y,q0.z,q0.w, q1.x,q1.y,q1.z,q1.w,
                             q2.x,q2.y,q2.z,q2.w, q3.x,q3.y,q3.z,q3.w,
                             q4.x,q4.y,q4.z,q4.w, q5.x,q5.y,q5.z,q5.w};
#pragma unroll
            for (int kx = 0; kx < 8; kx++) {
                const ulonglong2* wp =
                    (const ulonglong2*)(g_w1t + (c * 64 + ky * 8 + kx) * 32 + ocg * 8);
                ulonglong2 wa = wp[0], wb = wp[1];
#pragma unroll
                for (int px = 0; px < 5; px++) {
                    ull iv2 = pack2(row[px * 4 + kx]);
                    ffma2(acc[px][0], iv2, wa.x);
                    ffma2(acc[px][1], iv2, wa.y);
                    ffma2(acc[px][2], iv2, wb.x);
                    ffma2(acc[px][3], iv2, wb.y);
                }
            }
        }
    }
    size_t ob = (size_t)img * 12800 + oy * 20 + cc * 5;
#pragma unroll
    for (int j = 0; j < 4; j++) {
        int oc0 = ocg * 8 + 2 * j;
        float b0 = bias[oc0], b1 = bias[oc0 + 1];
#pragma unroll
        for (int px = 0; px < 5; px++) {
            float2 v = unpack2(acc[px][j]);
            float v0 = v.x + b0, v1 = v.y + b1;
            g_act1[ob + (size_t)oc0 * 400 + px]       = v0 > 0.f ? v0 : 0.f;
            g_act1[ob + (size_t)(oc0 + 1) * 400 + px] = v1 > 0.f ? v1 : 0.f;
        }
    }
}

// ---------------- conv2: 32->64, 4x4, stride 2, 20x20 -> 9x9 ----------------
// 4 images/block, 288 threads = (il 0..3) x (ocg 0..7 of 8 oc) x (oy 0..8)
__global__ void __launch_bounds__(288, 1) conv2_kernel(const float* __restrict__ bias) {
    extern __shared__ float sm[];            // 4 * 12800 floats
    int img0 = blockIdx.x * 4;
    float4* in4 = (float4*)sm;
    const float4* src4 = (const float4*)(g_act1 + (size_t)img0 * 12800);
    for (int i = threadIdx.x; i < 12800; i += 288) in4[i] = src4[i];
    __syncthreads();

    int il  = threadIdx.x / 72;
    int r   = threadIdx.x % 72;
    int ocg = r / 9, oy = r % 9;

    ull acc[9][4];
#pragma unroll
    for (int p = 0; p < 9; p++)
#pragma unroll
        for (int j = 0; j < 4; j++) acc[p][j] = 0ull;

#pragma unroll 1
    for (int c = 0; c < 32; c++) {
#pragma unroll 1
        for (int ky = 0; ky < 4; ky++) {
            int iy = oy * 2 + ky;
            const float4* rp = in4 + il * 3200 + c * 100 + iy * 5;
            float4 q0 = rp[0], q1 = rp[1], q2 = rp[2], q3 = rp[3], q4 = rp[4];
            float row[20] = {q0.x,q0.y,q0.z,q0.w, q1.x,q1.y,q1.z,q1.w,
                             q2.x,q2.y,q2.z,q2.w, q3.x,q3.y,q3.z,q3.w,
                             q4.x,q4.y,q4.z,q4.w};
#pragma unroll
            for (int kx = 0; kx < 4; kx++) {
                const ulonglong2* wp =
                    (const ulonglong2*)(g_w2t + (c * 16 + ky * 4 + kx) * 64 + ocg * 8);
                ulonglong2 wa = wp[0], wb = wp[1];
#pragma unroll
                for (int px = 0; px < 9; px++) {
                    ull iv2 = pack2(row[px * 2 + kx]);
                    ffma2(acc[px][0], iv2, wa.x);
                    ffma2(acc[px][1], iv2, wa.y);
                    ffma2(acc[px][2], iv2, wb.x);
                    ffma2(acc[px][3], iv2, wb.y);
                }
            }
        }
    }
    size_t ob = (size_t)(img0 + il) * 5184 + oy * 9;
#pragma unroll
    for (int j = 0; j < 4; j++) {
        int oc0 = ocg * 8 + 2 * j;
        float b0 = bias[oc0], b1 = bias[oc0 + 1];
#pragma unroll
        for (int px = 0; px < 9; px++) {
            float2 v = unpack2(acc[px][j]);
            float v0 = v.x + b0, v1 = v.y + b1;
            g_act2[ob + (size_t)oc0 * 81 + px]       = v0 > 0.f ? v0 : 0.f;
            g_act2[ob + (size_t)(oc0 + 1) * 81 + px] = v1 > 0.f ? v1 : 0.f;
        }
    }
}

// ---------------- conv3: 64->64, 3x3, stride 1, 9x9 -> 7x7 ----------------
// 8 images/block, 448 threads = (il 0..7) x (ocg 0..7) x (oy 0..6)
// smem rows padded to 12 floats (48B) so each row = 3 aligned float4 loads
__global__ void __launch_bounds__(448, 1) conv3_kernel(const float* __restrict__ bias) {
    extern __shared__ float sm[];            // 8 * 6912 floats
    int img0 = blockIdx.x * 8;
    for (int i = threadIdx.x; i < 41472; i += 448) {
        int il = i / 5184, rm = i % 5184;    // rm = c*81 + iy*9 + ixx
        int c = rm / 81, r2 = rm % 81;
        int iy = r2 / 9, ixx = r2 % 9;
        sm[il * 6912 + (c * 9 + iy) * 12 + ixx] =
            g_act2[(size_t)(img0 + il) * 5184 + rm];
    }
    __syncthreads();

    int il  = threadIdx.x / 56;
    int r   = threadIdx.x % 56;
    int ocg = r / 7, oy = r % 7;

    ull acc[7][4];
#pragma unroll
    for (int p = 0; p < 7; p++)
#pragma unroll
        for (int j = 0; j < 4; j++) acc[p][j] = 0ull;

#pragma unroll 1
    for (int c = 0; c < 64; c++) {
#pragma unroll
        for (int ky = 0; ky < 3; ky++) {
            int iy = oy + ky;
            const float4* rp = (const float4*)sm + il * 1728 + (c * 9 + iy) * 3;
            float4 q0 = rp[0], q1 = rp[1], q2 = rp[2];
            float row[12] = {q0.x,q0.y,q0.z,q0.w, q1.x,q1.y,q1.z,q1.w,
                             q2.x,q2.y,q2.z,q2.w};
            ull iv2[9];
#pragma unroll
            for (int i = 0; i < 9; i++) iv2[i] = pack2(row[i]);
#pragma unroll
            for (int kx = 0; kx < 3; kx++) {
                const ulonglong2* wp =
                    (const ulonglong2*)(g_w3t + (c * 9 + ky * 3 + kx) * 64 + ocg * 8);
                ulonglong2 wa = wp[0], wb = wp[1];
#pragma unroll
                for (int px = 0; px < 7; px++) {
                    ffma2(acc[px][0], iv2[px + kx], wa.x);
                    ffma2(acc[px][1], iv2[px + kx], wa.y);
                    ffma2(acc[px][2], iv2[px + kx], wb.x);
                    ffma2(acc[px][3], iv2[px + kx], wb.y);
                }
            }
        }
    }
    size_t ob = (size_t)(img0 + il) * 3136 + oy * 7;
#pragma unroll
    for (int j = 0; j < 4; j++) {
        int oc0 = ocg * 8 + 2 * j;
        float b0 = bias[oc0], b1 = bias[oc0 + 1];
#pragma unroll
        for (int px = 0; px < 7; px++) {
            float2 v = unpack2(acc[px][j]);
            float v0 = v.x + b0, v1 = v.y + b1;
            g_act3[ob + (size_t)oc0 * 49 + px]       = v0 > 0.f ? v0 : 0.f;
            g_act3[ob + (size_t)(oc0 + 1) * 49 + px] = v1 > 0.f ? v1 : 0.f;
        }
    }
}

// ---------------- generic GEMM: C[M,N] = A[M,K] @ W[N,K]^T (+bias)(+act) ----------------
template<int ACT>
__global__ void __launch_bounds__(256) gemm_tn(const float* __restrict__ A, int lda,
                                               const float* __restrict__ W, int ldw,
                                               const float* __restrict__ bias,
                                               float* __restrict__ C, int ldc,
                                               int M, int N, int K) {
    __shared__ float As[32][33];
    __shared__ float Ws[64][33];
    int row0 = blockIdx.x * 32, col0 = blockIdx.y * 64;
    int tx = threadIdx.x & 15;
    int ty = threadIdx.x >> 4;
    float acc[2][4] = {};
    for (int k0 = 0; k0 < K; k0 += 32) {
#pragma unroll
        for (int e = 0; e < 4; e++) {
            int idx = threadIdx.x + e * 256;
            int r = idx >> 5, cc = idx & 31;
            As[r][cc] = (row0 + r < M && k0 + cc < K) ? A[(size_t)(row0 + r) * lda + k0 + cc] : 0.f;
        }
#pragma unroll
        for (int e = 0; e < 8; e++) {
            int idx = threadIdx.x + e * 256;
            int r = idx >> 5, cc = idx & 31;
            Ws[r][cc] = (col0 + r < N && k0 + cc < K) ? W[(size_t)(col0 + r) * ldw + k0 + cc] : 0.f;
        }
        __syncthreads();
#pragma unroll
        for (int kk = 0; kk < 32; kk++) {
            float a0 = As[ty * 2 + 0][kk];
            float a1 = As[ty * 2 + 1][kk];
            float b0 = Ws[tx * 4 + 0][kk];
            float b1 = Ws[tx * 4 + 1][kk];
            float b2 = Ws[tx * 4 + 2][kk];
            float b3 = Ws[tx * 4 + 3][kk];
            acc[0][0] += a0 * b0; acc[0][1] += a0 * b1; acc[0][2] += a0 * b2; acc[0][3] += a0 * b3;
            acc[1][0] += a1 * b0; acc[1][1] += a1 * b1; acc[1][2] += a1 * b2; acc[1][3] += a1 * b3;
        }
        __syncthreads();
    }
#pragma unroll
    for (int i = 0; i < 2; i++) {
        int r = row0 + ty * 2 + i;
        if (r >= M) continue;
#pragma unroll
        for (int j = 0; j < 4; j++) {
            int cc = col0 + tx * 4 + j;
            if (cc >= N) continue;
            float v = acc[i][j];
            if (bias) v += bias[cc];
            if (ACT == 1) v = (v > 20.f) ? v : log1pf(__expf(v));  // softplus
            C[(size_t)r * ldc + cc] = v;
        }
    }
}

// ---------------- causal depthwise conv1d + silu ----------------
__global__ void conv1d_silu(const float* __restrict__ w, const float* __restrict__ b) {
    int idx = blockIdx.x * 256 + threadIdx.x;
    if (idx >= BS * 256) return;
    int bs = idx >> 8;        // frame
    int d  = idx & 255;
    int bb = bs >> 5, s = bs & 31;
    float acc = b[d];
#pragma unroll
    for (int k = 0; k < 4; k++) {
        int si = s - 3 + k;
        if (si >= 0) acc += g_xz[(size_t)(bb * 32 + si) * 512 + d] * w[d * 4 + k];
    }
    g_u[(size_t)bs * 256 + d] = acc / (1.f + __expf(-acc));
}

// ---------------- selective scan; contract with C only at t=S-1 ----------------
__global__ void scan_kernel(const float* __restrict__ A_log, const float* __restrict__ Dv) {
    int w = blockIdx.x * 8 + (threadIdx.x >> 5);
    int lane = threadIdx.x & 31;
    int bb = w >> 8, d = w & 255;
    float An = -__expf(A_log[d * 32 + lane]);
    float h = 0.f;
#pragma unroll 4
    for (int t = 0; t < 32; t++) {
        size_t bs = (size_t)(bb * 32 + t);
        float dtv = g_dt[bs * 256 + d];
        float uv  = g_u [bs * 256 + d];
        float Bv  = g_xdbl[bs * 72 + 8 + lane];
        h = __expf(dtv * An) * h + (dtv * uv) * Bv;
    }
    size_t bs_last = (size_t)(bb * 32 + 31);
    float Cv = g_xdbl[bs_last * 72 + 40 + lane];
    float y = h * Cv;
#pragma unroll
    for (int o = 16; o; o >>= 1) y += __shfl_xor_sync(0xffffffffu, y, o);
    if (lane == 0) {
        float ul = g_u[bs_last * 256 + d];
        y += Dv[d] * ul;
        float z = g_xz[bs_last * 512 + 256 + d];
        y *= z / (1.f + __expf(-z));
        g_yg[bb * 256 + d] = y;
    }
}

// ---------------- heads: out_proj (last step) + fc1 + fc2 + q ----------------
__global__ void __launch_bounds__(128) heads_kernel(
        const float* __restrict__ op_w,
        const float* __restrict__ fc1_w, const float* __restrict__ fc1_b,
        const float* __restrict__ fc2_w, const float* __restrict__ fc2_b,
        const float* __restrict__ q_w,  const float* __restrict__ q_b,
        float* __restrict__ out) {
    int b = blockIdx.x, tid = threadIdx.x;
    __shared__ float yg[256], lat[128], h1[128], h2[128];
    yg[tid]       = g_yg[b * 256 + tid];
    yg[tid + 128] = g_yg[b * 256 + tid + 128];
    __syncthreads();
    float acc = 0.f;
#pragma unroll 8
    for (int k = 0; k < 256; k++) acc += op_w[tid * 256 + k] * yg[k];
    lat[tid] = acc;
    out[NB * NA + b * 128 + tid] = acc;    // latent region after q region
    __syncthreads();
    acc = fc1_b[tid];
#pragma unroll 8
    for (int k = 0; k < 128; k++) acc += fc1_w[tid * 128 + k] * lat[k];
    h1[tid] = acc > 0.f ? acc : 0.f;
    __syncthreads();
    acc = fc2_b[tid];
#pragma unroll 8
    for (int k = 0; k < 128; k++) acc += fc2_w[tid * 128 + k] * h1[k];
    h2[tid] = acc > 0.f ? acc : 0.f;
    __syncthreads();
    if (tid < NA) {
        acc = q_b[tid];
#pragma unroll 8
        for (int k = 0; k < 128; k++) acc += q_w[tid * 128 + k] * h2[k];
        out[b * NA + tid] = acc;
    }
}

// ---------------- host launcher ----------------
extern "C" void kernel_launch(void* const* d_in, const int* in_sizes, int n_in,
                              void* d_out, int out_size) {
    const float* x         = (const float*)d_in[0];
    const float* conv1_w   = (const float*)d_in[1];
    const float* conv1_b   = (const float*)d_in[2];
    const float* conv2_w   = (const float*)d_in[3];
    const float* conv2_b   = (const float*)d_in[4];
    const float* conv3_w   = (const float*)d_in[5];
    const float* conv3_b   = (const float*)d_in[6];
    const float* feat_w    = (const float*)d_in[7];
    const float* feat_b    = (const float*)d_in[8];
    const float* in_proj_w = (const float*)d_in[9];
    const float* conv1d_w  = (const float*)d_in[10];
    const float* conv1d_b  = (const float*)d_in[11];
    const float* x_proj_w  = (const float*)d_in[12];
    const float* dt_proj_w = (const float*)d_in[13];
    const float* dt_proj_b = (const float*)d_in[14];
    const float* A_log     = (const float*)d_in[15];
    const float* Dvec      = (const float*)d_in[16];
    const float* out_proj_w= (const float*)d_in[17];
    const float* fc1_w     = (const float*)d_in[18];
    const float* fc1_b     = (const float*)d_in[19];
    const float* fc2_w     = (const float*)d_in[20];
    const float* fc2_b     = (const float*)d_in[21];
    const float* q_w       = (const float*)d_in[22];
    const float* q_b       = (const float*)d_in[23];
    float* out = (float*)d_out;

    // Resolve real device addresses of __device__ globals (host shadow trap on GB300/ATS).
    float *p_act3, *p_feat, *p_xz, *p_u, *p_xdbl, *p_dt;
    cudaGetSymbolAddress((void**)&p_act3, g_act3);
    cudaGetSymbolAddress((void**)&p_feat, g_feat);
    cudaGetSymbolAddress((void**)&p_xz,   g_xz);
    cudaGetSymbolAddress((void**)&p_u,    g_u);
    cudaGetSymbolAddress((void**)&p_xdbl, g_xdbl);
    cudaGetSymbolAddress((void**)&p_dt,   g_dt);

    cudaFuncSetAttribute(conv1_kernel, cudaFuncAttributeMaxDynamicSharedMemorySize, 112896);
    cudaFuncSetAttribute(conv2_kernel, cudaFuncAttributeMaxDynamicSharedMemorySize, 204800);
    cudaFuncSetAttribute(conv3_kernel, cudaFuncAttributeMaxDynamicSharedMemorySize, 221184);

    prep_weights<<<304, 256>>>(conv1_w, conv2_w, conv3_w);
    conv1_kernel<<<BS, 320, 112896>>>(x, conv1_b);
    conv2_kernel<<<BS / 4, 288, 204800>>>(conv2_b);
    conv3_kernel<<<BS / 8, 448, 221184>>>(conv3_b);

    // feat: (2048 x 3136) @ (128 x 3136)^T + bias
    gemm_tn<0><<<dim3(64, 2), 256>>>(p_act3, 3136, feat_w, 3136, feat_b, p_feat, 128,
                                     BS, 128, 3136);
    // in_proj: (2048 x 128) @ (512 x 128)^T
    gemm_tn<0><<<dim3(64, 8), 256>>>(p_feat, 128, in_proj_w, 128, (const float*)nullptr,
                                     p_xz, 512, BS, 512, 128);
    conv1d_silu<<<(BS * 256 + 255) / 256, 256>>>(conv1d_w, conv1d_b);
    // x_proj: (2048 x 256) @ (72 x 256)^T
    gemm_tn<0><<<dim3(64, 2), 256>>>(p_u, 256, x_proj_w, 256, (const float*)nullptr,
                                     p_xdbl, 72, BS, 72, 256);
    // dt: (2048 x 8) @ (256 x 8)^T + bias, softplus
    gemm_tn<1><<<dim3(64, 4), 256>>>(p_xdbl, 72, dt_proj_w, 8, dt_proj_b,
                                     p_dt, 256, BS, 256, 8);
    scan_kernel<<<BS, 256>>>(A_log, Dvec);
    heads_kernel<<<NB, 128>>>(out_proj_w, fc1_w, fc1_b, fc2_w, fc2_b, q_w, q_b, out);
}

// round 5
// speedup vs baseline: 2.1238x; 1.3423x over previous
#include <cuda_runtime.h>
#include <cuda_bf16.h>
#include <math.h>

// ---------------- problem constants ----------------
#define NB    64
#define NS    32
#define BS    2048            // NB*NS frames
#define D_MODEL 128
#define D_STATE 32
#define D_CONV  4
#define D_INNER 256
#define DT_RANK 8
#define CNN_OUT 3136
#define NA    18
#define INV255 (1.0f/255.0f)

typedef unsigned long long ull;
typedef unsigned int uint;

// ---------------- scratch (static device globals; no allocation) ----------------
__device__ __nv_bfloat16 g_a1h[(size_t)BS*12800];   // conv1 out NHWC hi [img][px400][c32]
__device__ __nv_bfloat16 g_a1l[(size_t)BS*12800];   // conv1 out NHWC lo
__device__ __nv_bfloat16 g_a2h[(size_t)BS*5184];    // conv2 out NHWC hi [img][px81][c64]
__device__ __nv_bfloat16 g_a2l[(size_t)BS*5184];    // conv2 out NHWC lo
__device__ float g_act3[(size_t)BS*3136];           // conv3 out fp32 NCHW-flat [img][oc*49+px]
__device__ float g_feat[(size_t)BS*128];
__device__ float g_xz  [(size_t)BS*512];
__device__ float g_u   [(size_t)BS*256];
__device__ float g_xdbl[(size_t)BS*72];
__device__ float g_dt  [(size_t)BS*256];
__device__ float g_yg  [NB*256];
// prepacked weights in mma B-fragment order: uint4 {b0hi, b1hi, b0lo, b1lo}
__device__ uint4 g_wp1[16*4*32];    // conv1: 16 k-steps x 4 n-tiles x 32 lanes
__device__ uint4 g_wp2[32*8*32];    // conv2: 32 x 8 x 32
__device__ uint4 g_wp3[36*8*32];    // conv3: 36 x 8 x 32

// ---------------- helpers ----------------
__device__ __forceinline__ void bfsplit(float v, __nv_bfloat16& h, __nv_bfloat16& l) {
    h = __float2bfloat16_rn(v);
    l = __float2bfloat16_rn(v - __bfloat162float(h));
}
__device__ __forceinline__ uint packbf2(__nv_bfloat16 a, __nv_bfloat16 b) {
    __nv_bfloat162 t; t.x = a; t.y = b;      // .x -> low 16 bits (lower k / lower addr)
    return *reinterpret_cast<uint*>(&t);
}
__device__ __forceinline__ void mma_bf(float* d, uint a0, uint a1, uint a2, uint a3,
                                       uint b0, uint b1) {
    asm("mma.sync.aligned.m16n8k16.row.col.f32.bf16.bf16.f32 "
        "{%0,%1,%2,%3}, {%4,%5,%6,%7}, {%8,%9}, {%0,%1,%2,%3};"
        : "+f"(d[0]), "+f"(d[1]), "+f"(d[2]), "+f"(d[3])
        : "r"(a0), "r"(a1), "r"(a2), "r"(a3), "r"(b0), "r"(b1));
}

// ---------------- weight prepack (once per launch) ----------------
// For step s, n-tile j, lane: B frag b0 = B[tg*2, j*8+g],B[tg*2+1,...]; b1 rows +8.
__global__ void prep_wpack(const float* __restrict__ w1,
                           const float* __restrict__ w2,
                           const float* __restrict__ w3) {
    int idx = blockIdx.x * 256 + threadIdx.x;
    float v[4];
    if (idx < 2048) {                         // conv1
        int lane = idx & 31, j = (idx >> 5) & 3, s = idx >> 7;
        int g = lane >> 2, tg = lane & 3, oc = j * 8 + g;
        int ky = s >> 1, cc = s & 1;
#pragma unroll
        for (int q = 0; q < 4; q++) {
            int r = (q < 2) ? tg * 2 + q : tg * 2 + 6 + q;   // tg*2, +1, +8, +9
            int kxl = r >> 2, c = r & 3;
            v[q] = w1[oc * 256 + c * 64 + ky * 8 + cc * 4 + kxl];
        }
        __nv_bfloat16 h[4], l[4];
#pragma unroll
        for (int q = 0; q < 4; q++) bfsplit(v[q], h[q], l[q]);
        g_wp1[idx] = make_uint4(packbf2(h[0],h[1]), packbf2(h[2],h[3]),
                                packbf2(l[0],l[1]), packbf2(l[2],l[3]));
    } else if (idx < 2048 + 8192) {           // conv2
        int i = idx - 2048;
        int lane = i & 31, j = (i >> 5) & 7, s = i >> 8;
        int g = lane >> 2, tg = lane & 3, oc = j * 8 + g;
        int tap = s >> 1, cc = s & 1;
        int ky = tap >> 2, kx = tap & 3;
#pragma unroll
        for (int q = 0; q < 4; q++) {
            int r = (q < 2) ? tg * 2 + q : tg * 2 + 6 + q;
            int c = cc * 16 + r;
            v[q] = w2[oc * 512 + c * 16 + ky * 4 + kx];
        }
        __nv_bfloat16 h[4], l[4];
#pragma unroll
        for (int q = 0; q < 4; q++) bfsplit(v[q], h[q], l[q]);
        g_wp2[i] = make_uint4(packbf2(h[0],h[1]), packbf2(h[2],h[3]),
                              packbf2(l[0],l[1]), packbf2(l[2],l[3]));
    } else if (idx < 2048 + 8192 + 9216) {    // conv3
        int i = idx - 10240;
        int lane = i & 31, j = (i >> 5) & 7, s = i >> 8;
        int g = lane >> 2, tg = lane & 3, oc = j * 8 + g;
        int tap = s >> 2, cc = s & 3;
        int ky = tap / 3, kx = tap % 3;
#pragma unroll
        for (int q = 0; q < 4; q++) {
            int r = (q < 2) ? tg * 2 + q : tg * 2 + 6 + q;
            int c = cc * 16 + r;
            v[q] = w3[oc * 576 + c * 9 + ky * 3 + kx];
        }
        __nv_bfloat16 h[4], l[4];
#pragma unroll
        for (int q = 0; q < 4; q++) bfsplit(v[q], h[q], l[q]);
        g_wp3[i] = make_uint4(packbf2(h[0],h[1]), packbf2(h[2],h[3]),
                              packbf2(l[0],l[1]), packbf2(l[2],l[3]));
    }
}

// ---------------- conv1: 4->32, 8x8, s4 | GEMM M=400 N=32 K=256 ----------------
// 1 img/block, 800 thr = 25 warps, warp = 1 m-tile (16 px) x 4 n-tiles x 16 k-steps
// smem: NHWC bf16 hi plane (28224 el) + lo plane
__global__ void __launch_bounds__(800) conv1_mma(const float* __restrict__ x,
                                                 const float* __restrict__ bias) {
    extern __shared__ __nv_bfloat16 sm[];
    __nv_bfloat16* smh = sm;
    __nv_bfloat16* sml = sm + 28224;
    int img = blockIdx.x;
    const float4* xin4 = (const float4*)(x + (size_t)img * 28224);
    for (int i = threadIdx.x; i < 7056; i += 800) {
        int c = i / 1764, p4 = i % 1764;
        float4 v4 = xin4[i];
        float vv[4] = {v4.x, v4.y, v4.z, v4.w};
#pragma unroll
        for (int jj = 0; jj < 4; jj++) {
            int px = p4 * 4 + jj;
            __nv_bfloat16 h, l;
            bfsplit(vv[jj] * INV255, h, l);
            smh[px * 4 + c] = h;
            sml[px * 4 + c] = l;
        }
    }
    __syncthreads();

    int warp = threadIdx.x >> 5, lane = threadIdx.x & 31;
    int g = lane >> 2, tg = lane & 3;
    int r0 = warp * 16 + g, r1 = r0 + 8;     // px rows, all < 400
    int ba0 = (r0 / 20) * 1344 + (r0 % 20) * 16;   // element index
    int ba1 = (r1 / 20) * 1344 + (r1 % 20) * 16;

    float acc[4][4];
#pragma unroll
    for (int j = 0; j < 4; j++)
#pragma unroll
        for (int q = 0; q < 4; q++) acc[j][q] = 0.f;

    int s = 0;
#pragma unroll 1
    for (int ky = 0; ky < 8; ky++) {
#pragma unroll
        for (int cc = 0; cc < 2; cc++, s++) {
            int off = ky * 336 + cc * 16 + tg * 2;
            uint a0 = *(const uint*)(smh + ba0 + off);
            uint a1 = *(const uint*)(smh + ba1 + off);
            uint a2 = *(const uint*)(smh + ba0 + off + 8);
            uint a3 = *(const uint*)(smh + ba1 + off + 8);
            uint l0 = *(const uint*)(sml + ba0 + off);
            uint l1 = *(const uint*)(sml + ba1 + off);
            uint l2 = *(const uint*)(sml + ba0 + off + 8);
            uint l3 = *(const uint*)(sml + ba1 + off + 8);
            uint4 wq[4];
#pragma unroll
            for (int j = 0; j < 4; j++) wq[j] = g_wp1[(s * 4 + j) * 32 + lane];
#pragma unroll
            for (int j = 0; j < 4; j++) {
                mma_bf(acc[j], a0, a1, a2, a3, wq[j].x, wq[j].y);  // hi*hi
                mma_bf(acc[j], a0, a1, a2, a3, wq[j].z, wq[j].w);  // hi*lo
                mma_bf(acc[j], l0, l1, l2, l3, wq[j].x, wq[j].y);  // lo*hi
            }
        }
    }
    // epilogue: bias + relu + bf16 split, NHWC out [px][c32]
    size_t ob = (size_t)img * 12800;
#pragma unroll
    for (int j = 0; j < 4; j++) {
        int oc = j * 8 + tg * 2;
        float b0 = bias[oc], b1 = bias[oc + 1];
        float v00 = acc[j][0] + b0, v01 = acc[j][1] + b1;
        float v10 = acc[j][2] + b0, v11 = acc[j][3] + b1;
        v00 = v00 > 0.f ? v00 : 0.f; v01 = v01 > 0.f ? v01 : 0.f;
        v10 = v10 > 0.f ? v10 : 0.f; v11 = v11 > 0.f ? v11 : 0.f;
        __nv_bfloat16 h0,l0_,h1,l1_,h2,l2_,h3,l3_;
        bfsplit(v00,h0,l0_); bfsplit(v01,h1,l1_);
        bfsplit(v10,h2,l2_); bfsplit(v11,h3,l3_);
        *(uint*)(g_a1h + ob + r0 * 32 + oc) = packbf2(h0, h1);
        *(uint*)(g_a1l + ob + r0 * 32 + oc) = packbf2(l0_, l1_);
        *(uint*)(g_a1h + ob + r1 * 32 + oc) = packbf2(h2, h3);
        *(uint*)(g_a1l + ob + r1 * 32 + oc) = packbf2(l2_, l3_);
    }
}

// ---------------- conv2: 32->64, 4x4, s2 | GEMM M=81(pad96) N=64 K=512 ----------------
// 1 img/block, 192 thr = 6 warps, warp = 1 m-tile x 8 n-tiles x 32 k-steps
// smem: NHWC padded px-stride 40 el (bank-conflict-free fragments)
__global__ void __launch_bounds__(192) conv2_mma(const float* __restrict__ bias) {
    extern __shared__ __nv_bfloat16 sm[];
    __nv_bfloat16* smh = sm;                 // 400*40 = 16000 el
    __nv_bfloat16* sml = sm + 16000;
    int img = blockIdx.x;
    for (int i = threadIdx.x; i < 3200; i += 192) {
        int px = i >> 3, cc = i & 7;
        ull vh = ((const ull*)g_a1h)[(size_t)img * 3200 + i];
        ull vl = ((const ull*)g_a1l)[(size_t)img * 3200 + i];
        *(ull*)(smh + px * 40 + cc * 4) = vh;
        *(ull*)(sml + px * 40 + cc * 4) = vl;
    }
    __syncthreads();

    int warp = threadIdx.x >> 5, lane = threadIdx.x & 31;
    int g = lane >> 2, tg = lane & 3;
    int r0 = warp * 16 + g, r1 = r0 + 8;
    int p0 = min(r0, 80), p1 = min(r1, 80);
    int ba0 = ((p0 / 9) * 40 + (p0 % 9) * 2) * 40;   // ((oy*2)*20 + ox*2)*40
    int ba1 = ((p1 / 9) * 40 + (p1 % 9) * 2) * 40;

    float acc[8][4];
#pragma unroll
    for (int j = 0; j < 8; j++)
#pragma unroll
        for (int q = 0; q < 4; q++) acc[j][q] = 0.f;

    int s = 0;
#pragma unroll 1
    for (int ky = 0; ky < 4; ky++) {
#pragma unroll 1
        for (int kx = 0; kx < 4; kx++) {
            int toff = (ky * 20 + kx) * 40;
#pragma unroll
            for (int cc = 0; cc < 2; cc++, s++) {
                int off = toff + cc * 16 + tg * 2;
                uint a0 = *(const uint*)(smh + ba0 + off);
                uint a1 = *(const uint*)(smh + ba1 + off);
                uint a2 = *(const uint*)(smh + ba0 + off + 8);
                uint a3 = *(const uint*)(smh + ba1 + off + 8);
                uint l0 = *(const uint*)(sml + ba0 + off);
                uint l1 = *(const uint*)(sml + ba1 + off);
                uint l2 = *(const uint*)(sml + ba0 + off + 8);
                uint l3 = *(const uint*)(sml + ba1 + off + 8);
                uint4 wq[8];
#pragma unroll
                for (int j = 0; j < 8; j++) wq[j] = g_wp2[(s * 8 + j) * 32 + lane];
#pragma unroll
                for (int j = 0; j < 8; j++) {
                    mma_bf(acc[j], a0, a1, a2, a3, wq[j].x, wq[j].y);
                    mma_bf(acc[j], a0, a1, a2, a3, wq[j].z, wq[j].w);
                    mma_bf(acc[j], l0, l1, l2, l3, wq[j].x, wq[j].y);
                }
            }
        }
    }
    size_t ob = (size_t)img * 5184;
#pragma unroll
    for (int j = 0; j < 8; j++) {
        int oc = j * 8 + tg * 2;
        float b0 = bias[oc], b1 = bias[oc + 1];
        if (r0 < 81) {
            float v0 = acc[j][0] + b0, v1 = acc[j][1] + b1;
            v0 = v0 > 0.f ? v0 : 0.f; v1 = v1 > 0.f ? v1 : 0.f;
            __nv_bfloat16 h0,l0_,h1,l1_;
            bfsplit(v0,h0,l0_); bfsplit(v1,h1,l1_);
            *(uint*)(g_a2h + ob + r0 * 64 + oc) = packbf2(h0, h1);
            *(uint*)(g_a2l + ob + r0 * 64 + oc) = packbf2(l0_, l1_);
        }
        if (r1 < 81) {
            float v0 = acc[j][2] + b0, v1 = acc[j][3] + b1;
            v0 = v0 > 0.f ? v0 : 0.f; v1 = v1 > 0.f ? v1 : 0.f;
            __nv_bfloat16 h0,l0_,h1,l1_;
            bfsplit(v0,h0,l0_); bfsplit(v1,h1,l1_);
            *(uint*)(g_a2h + ob + r1 * 64 + oc) = packbf2(h0, h1);
            *(uint*)(g_a2l + ob + r1 * 64 + oc) = packbf2(l0_, l1_);
        }
    }
}

// ---------------- conv3: 64->64, 3x3, s1 | GEMM M=49(pad64) N=64 K=576 ----------------
// 4 img/block, 512 thr = 16 warps = 4 img x 4 m-tiles; px-stride 72 el
__global__ void __launch_bounds__(512) conv3_mma(const float* __restrict__ bias) {
    extern __shared__ __nv_bfloat16 sm[];
    const int PS = 5832;                      // 81*72 padded els per image
    __nv_bfloat16* smh = sm;
    __nv_bfloat16* sml = sm + 4 * PS;
    int img0 = blockIdx.x * 4;
    for (int i = threadIdx.x; i < 4 * 1296; i += 512) {
        int il = i / 1296, r = i % 1296;
        int px = r >> 4, cc = r & 15;
        ull vh = ((const ull*)g_a2h)[(size_t)(img0 + il) * 1296 + r];
        ull vl = ((const ull*)g_a2l)[(size_t)(img0 + il) * 1296 + r];
        *(ull*)(smh + il * PS + px * 72 + cc * 4) = vh;
        *(ull*)(sml + il * PS + px * 72 + cc * 4) = vl;
    }
    __syncthreads();

    int warp = threadIdx.x >> 5, lane = threadIdx.x & 31;
    int il = warp >> 2, tile = warp & 3;
    int g = lane >> 2, tg = lane & 3;
    int img = img0 + il;
    int r0 = tile * 16 + g, r1 = r0 + 8;
    int p0 = min(r0, 48), p1 = min(r1, 48);
    const __nv_bfloat16* bh = smh + il * PS;
    const __nv_bfloat16* bl = sml + il * PS;
    int ba0 = ((p0 / 7) * 9 + (p0 % 7)) * 72;
    int ba1 = ((p1 / 7) * 9 + (p1 % 7)) * 72;

    float acc[8][4];
#pragma unroll
    for (int j = 0; j < 8; j++)
#pragma unroll
        for (int q = 0; q < 4; q++) acc[j][q] = 0.f;

    int s = 0;
#pragma unroll 1
    for (int ky = 0; ky < 3; ky++) {
#pragma unroll 1
        for (int kx = 0; kx < 3; kx++) {
            int toff = (ky * 9 + kx) * 72;
#pragma unroll
            for (int cc = 0; cc < 4; cc++, s++) {
                int off = toff + cc * 16 + tg * 2;
                uint a0 = *(const uint*)(bh + ba0 + off);
                uint a1 = *(const uint*)(bh + ba1 + off);
                uint a2 = *(const uint*)(bh + ba0 + off + 8);
                uint a3 = *(const uint*)(bh + ba1 + off + 8);
                uint l0 = *(const uint*)(bl + ba0 + off);
                uint l1 = *(const uint*)(bl + ba1 + off);
                uint l2 = *(const uint*)(bl + ba0 + off + 8);
                uint l3 = *(const uint*)(bl + ba1 + off + 8);
                uint4 wq[8];
#pragma unroll
                for (int j = 0; j < 8; j++) wq[j] = g_wp3[(s * 8 + j) * 32 + lane];
#pragma unroll
                for (int j = 0; j < 8; j++) {
                    mma_bf(acc[j], a0, a1, a2, a3, wq[j].x, wq[j].y);
                    mma_bf(acc[j], a0, a1, a2, a3, wq[j].z, wq[j].w);
                    mma_bf(acc[j], l0, l1, l2, l3, wq[j].x, wq[j].y);
                }
            }
        }
    }
    // epilogue: fp32 NCHW-flat out for feat GEMM: [img][oc*49 + px]
    size_t ob = (size_t)img * 3136;
#pragma unroll
    for (int j = 0; j < 8; j++) {
        int oc = j * 8 + tg * 2;
        float b0 = bias[oc], b1 = bias[oc + 1];
        if (r0 < 49) {
            float v0 = acc[j][0] + b0, v1 = acc[j][1] + b1;
            g_act3[ob + (size_t)oc * 49 + r0]       = v0 > 0.f ? v0 : 0.f;
            g_act3[ob + (size_t)(oc + 1) * 49 + r0] = v1 > 0.f ? v1 : 0.f;
        }
        if (r1 < 49) {
            float v0 = acc[j][2] + b0, v1 = acc[j][3] + b1;
            g_act3[ob + (size_t)oc * 49 + r1]       = v0 > 0.f ? v0 : 0.f;
            g_act3[ob + (size_t)(oc + 1) * 49 + r1] = v1 > 0.f ? v1 : 0.f;
        }
    }
}

// ---------------- generic GEMM: C[M,N] = A[M,K] @ W[N,K]^T (+bias)(+act) ----------------
template<int ACT>
__global__ void __launch_bounds__(256) gemm_tn(const float* __restrict__ A, int lda,
                                               const float* __restrict__ W, int ldw,
                                               const float* __restrict__ bias,
                                               float* __restrict__ C, int ldc,
                                               int M, int N, int K) {
    __shared__ float As[32][33];
    __shared__ float Ws[64][33];
    int row0 = blockIdx.x * 32, col0 = blockIdx.y * 64;
    int tx = threadIdx.x & 15;
    int ty = threadIdx.x >> 4;
    float acc[2][4] = {};
    for (int k0 = 0; k0 < K; k0 += 32) {
#pragma unroll
        for (int e = 0; e < 4; e++) {
            int idx = threadIdx.x + e * 256;
            int r = idx >> 5, cc = idx & 31;
            As[r][cc] = (row0 + r < M && k0 + cc < K) ? A[(size_t)(row0 + r) * lda + k0 + cc] : 0.f;
        }
#pragma unroll
        for (int e = 0; e < 8; e++) {
            int idx = threadIdx.x + e * 256;
            int r = idx >> 5, cc = idx & 31;
            Ws[r][cc] = (col0 + r < N && k0 + cc < K) ? W[(size_t)(col0 + r) * ldw + k0 + cc] : 0.f;
        }
        __syncthreads();
#pragma unroll
        for (int kk = 0; kk < 32; kk++) {
            float a0 = As[ty * 2 + 0][kk];
            float a1 = As[ty * 2 + 1][kk];
            float b0 = Ws[tx * 4 + 0][kk];
            float b1 = Ws[tx * 4 + 1][kk];
            float b2 = Ws[tx * 4 + 2][kk];
            float b3 = Ws[tx * 4 + 3][kk];
            acc[0][0] += a0 * b0; acc[0][1] += a0 * b1; acc[0][2] += a0 * b2; acc[0][3] += a0 * b3;
            acc[1][0] += a1 * b0; acc[1][1] += a1 * b1; acc[1][2] += a1 * b2; acc[1][3] += a1 * b3;
        }
        __syncthreads();
    }
#pragma unroll
    for (int i = 0; i < 2; i++) {
        int r = row0 + ty * 2 + i;
        if (r >= M) continue;
#pragma unroll
        for (int j = 0; j < 4; j++) {
            int cc = col0 + tx * 4 + j;
            if (cc >= N) continue;
            float v = acc[i][j];
            if (bias) v += bias[cc];
            if (ACT == 1) v = (v > 20.f) ? v : log1pf(__expf(v));  // softplus
            C[(size_t)r * ldc + cc] = v;
        }
    }
}

// ---------------- causal depthwise conv1d + silu ----------------
__global__ void conv1d_silu(const float* __restrict__ w, const float* __restrict__ b) {
    int idx = blockIdx.x * 256 + threadIdx.x;
    if (idx >= BS * 256) return;
    int bs = idx >> 8;
    int d  = idx & 255;
    int bb = bs >> 5, s = bs & 31;
    float acc = b[d];
#pragma unroll
    for (int k = 0; k < 4; k++) {
        int si = s - 3 + k;
        if (si >= 0) acc += g_xz[(size_t)(bb * 32 + si) * 512 + d] * w[d * 4 + k];
    }
    g_u[(size_t)bs * 256 + d] = acc / (1.f + __expf(-acc));
}

// ---------------- selective scan; contract with C only at t=S-1 ----------------
__global__ void scan_kernel(const float* __restrict__ A_log, const float* __restrict__ Dv) {
    int w = blockIdx.x * 8 + (threadIdx.x >> 5);
    int lane = threadIdx.x & 31;
    int bb = w >> 8, d = w & 255;
    float An = -__expf(A_log[d * 32 + lane]);
    float h = 0.f;
#pragma unroll 4
    for (int t = 0; t < 32; t++) {
        size_t bs = (size_t)(bb * 32 + t);
        float dtv = g_dt[bs * 256 + d];
        float uv  = g_u [bs * 256 + d];
        float Bv  = g_xdbl[bs * 72 + 8 + lane];
        h = __expf(dtv * An) * h + (dtv * uv) * Bv;
    }
    size_t bs_last = (size_t)(bb * 32 + 31);
    float Cv = g_xdbl[bs_last * 72 + 40 + lane];
    float y = h * Cv;
#pragma unroll
    for (int o = 16; o; o >>= 1) y += __shfl_xor_sync(0xffffffffu, y, o);
    if (lane == 0) {
        float ul = g_u[bs_last * 256 + d];
        y += Dv[d] * ul;
        float z = g_xz[bs_last * 512 + 256 + d];
        y *= z / (1.f + __expf(-z));
        g_yg[bb * 256 + d] = y;
    }
}

// ---------------- heads: out_proj (last step) + fc1 + fc2 + q ----------------
__global__ void __launch_bounds__(128) heads_kernel(
        const float* __restrict__ op_w,
        const float* __restrict__ fc1_w, const float* __restrict__ fc1_b,
        const float* __restrict__ fc2_w, const float* __restrict__ fc2_b,
        const float* __restrict__ q_w,  const float* __restrict__ q_b,
        float* __restrict__ out) {
    int b = blockIdx.x, tid = threadIdx.x;
    __shared__ float yg[256], lat[128], h1[128], h2[128];
    yg[tid]       = g_yg[b * 256 + tid];
    yg[tid + 128] = g_yg[b * 256 + tid + 128];
    __syncthreads();
    float acc = 0.f;
#pragma unroll 8
    for (int k = 0; k < 256; k++) acc += op_w[tid * 256 + k] * yg[k];
    lat[tid] = acc;
    out[NB * NA + b * 128 + tid] = acc;
    __syncthreads();
    acc = fc1_b[tid];
#pragma unroll 8
    for (int k = 0; k < 128; k++) acc += fc1_w[tid * 128 + k] * lat[k];
    h1[tid] = acc > 0.f ? acc : 0.f;
    __syncthreads();
    acc = fc2_b[tid];
#pragma unroll 8
    for (int k = 0; k < 128; k++) acc += fc2_w[tid * 128 + k] * h1[k];
    h2[tid] = acc > 0.f ? acc : 0.f;
    __syncthreads();
    if (tid < NA) {
        acc = q_b[tid];
#pragma unroll 8
        for (int k = 0; k < 128; k++) acc += q_w[tid * 128 + k] * h2[k];
        out[b * NA + tid] = acc;
    }
}

// ---------------- host launcher ----------------
extern "C" void kernel_launch(void* const* d_in, const int* in_sizes, int n_in,
                              void* d_out, int out_size) {
    const float* x         = (const float*)d_in[0];
    const float* conv1_w   = (const float*)d_in[1];
    const float* conv1_b   = (const float*)d_in[2];
    const float* conv2_w   = (const float*)d_in[3];
    const float* conv2_b   = (const float*)d_in[4];
    const float* conv3_w   = (const float*)d_in[5];
    const float* conv3_b   = (const float*)d_in[6];
    const float* feat_w    = (const float*)d_in[7];
    const float* feat_b    = (const float*)d_in[8];
    const float* in_proj_w = (const float*)d_in[9];
    const float* conv1d_w  = (const float*)d_in[10];
    const float* conv1d_b  = (const float*)d_in[11];
    const float* x_proj_w  = (const float*)d_in[12];
    const float* dt_proj_w = (const float*)d_in[13];
    const float* dt_proj_b = (const float*)d_in[14];
    const float* A_log     = (const float*)d_in[15];
    const float* Dvec      = (const float*)d_in[16];
    const float* out_proj_w= (const float*)d_in[17];
    const float* fc1_w     = (const float*)d_in[18];
    const float* fc1_b     = (const float*)d_in[19];
    const float* fc2_w     = (const float*)d_in[20];
    const float* fc2_b     = (const float*)d_in[21];
    const float* q_w       = (const float*)d_in[22];
    const float* q_b       = (const float*)d_in[23];
    float* out = (float*)d_out;

    // Resolve real device addresses of __device__ globals (host shadow trap on GB300/ATS).
    float *p_act3, *p_feat, *p_xz, *p_u, *p_xdbl, *p_dt;
    cudaGetSymbolAddress((void**)&p_act3, g_act3);
    cudaGetSymbolAddress((void**)&p_feat, g_feat);
    cudaGetSymbolAddress((void**)&p_xz,   g_xz);
    cudaGetSymbolAddress((void**)&p_u,    g_u);
    cudaGetSymbolAddress((void**)&p_xdbl, g_xdbl);
    cudaGetSymbolAddress((void**)&p_dt,   g_dt);

    cudaFuncSetAttribute(conv1_mma, cudaFuncAttributeMaxDynamicSharedMemorySize, 112896);
    cudaFuncSetAttribute(conv2_mma, cudaFuncAttributeMaxDynamicSharedMemorySize, 64000);
    cudaFuncSetAttribute(conv3_mma, cudaFuncAttributeMaxDynamicSharedMemorySize, 93312);

    prep_wpack<<<(19456 + 255) / 256, 256>>>(conv1_w, conv2_w, conv3_w);
    conv1_mma<<<BS, 800, 112896>>>(x, conv1_b);
    conv2_mma<<<BS, 192, 64000>>>(conv2_b);
    conv3_mma<<<BS / 4, 512, 93312>>>(conv3_b);

    // feat: (2048 x 3136) @ (128 x 3136)^T + bias
    gemm_tn<0><<<dim3(64, 2), 256>>>(p_act3, 3136, feat_w, 3136, feat_b, p_feat, 128,
                                     BS, 128, 3136);
    // in_proj: (2048 x 128) @ (512 x 128)^T
    gemm_tn<0><<<dim3(64, 8), 256>>>(p_feat, 128, in_proj_w, 128, (const float*)nullptr,
                                     p_xz, 512, BS, 512, 128);
    conv1d_silu<<<(BS * 256 + 255) / 256, 256>>>(conv1d_w, conv1d_b);
    // x_proj: (2048 x 256) @ (72 x 256)^T
    gemm_tn<0><<<dim3(64, 2), 256>>>(p_u, 256, x_proj_w, 256, (const float*)nullptr,
                                     p_xdbl, 72, BS, 72, 256);
    // dt: (2048 x 8) @ (256 x 8)^T + bias, softplus
    gemm_tn<1><<<dim3(64, 4), 256>>>(p_xdbl, 72, dt_proj_w, 8, dt_proj_b,
                                     p_dt, 256, BS, 256, 8);
    scan_kernel<<<BS, 256>>>(A_log, Dvec);
    heads_kernel<<<NB, 128>>>(out_proj_w, fc1_w, fc1_b, fc2_w, fc2_b, q_w, q_b, out);
}